// round 14
// baseline (speedup 1.0000x reference)
#include <cuda_runtime.h>

// Problem constants (fixed by reference)
#define CN 64
#define HN 256
#define WN 256
#define L0N 1024
#define L1N 1024
#define AC (-0.75f)

#define JT 128     // j-tile width per block (one float4 per lane)
#define NB 256     // x0 bins
#define SROW 128   // floats per smem row; XOR quad swizzle f' = f ^ (x&31)
#define NWARP 32

// Precomputed y tap indices / weights
__device__ int4   g_yidx[L0N];
__device__ float4 g_ywt [L0N];
// x samples sorted by x0 bin
__device__ int    g_binstart[NB + 1];
__device__ float4 g_meta[L1N];        // (w0, w1, w2, bitcast(i)) sorted by bin
__device__ int    g_wstart[NWARP + 1];

// smem float offsets
#define OFF_SY   0
#define OFF_META (HN * SROW)              // 32768
#define OFF_BS   (OFF_META + L1N * 4)     // 36864
#define OFF_WS   (OFF_BS + NB + 1)        // 37121
#define SMEM_FLOATS (OFF_WS + NWARP + 1)  // 37154

__device__ __forceinline__ void cubic_w(float t, float* w) {
    // Matches reference _cubic_weights exactly (A = -0.75)
    float t2 = t * t;
    float t3 = t2 * t;
    w[0] = AC * (t3 - 2.0f * t2 + t);
    w[1] = (AC + 2.0f) * t3 - (AC + 3.0f) * t2 + 1.0f;
    float s  = 1.0f - t;
    float s2 = s * s;
    w[2] = (AC + 2.0f) * s2 * s - (AC + 3.0f) * s2 + 1.0f;
    float u = 1.0f + s;
    w[3] = AC * (u * u * u) - 5.0f * AC * (u * u) + 8.0f * AC * u - 4.0f * AC;
}

// Single-block prep: y tables + counting sort + balanced warp partition.
__global__ void prep_kernel(const float* __restrict__ g0,
                            const float* __restrict__ g1) {
    __shared__ int sh_hist[NB];
    __shared__ int sh_scan[NB];
    __shared__ int sh_base[NB];
    const int tid = threadIdx.x;   // 0..1023

    // --- y taps ---
    {
        float x  = (g0[tid] + 1.0f) * 0.5f * (float)(HN - 1);
        float x0 = floorf(x);
        float t  = x - x0;
        int  i0  = (int)x0;
        float w[4];
        cubic_w(t, w);
        int idx[4];
#pragma unroll
        for (int b = 0; b < 4; b++) idx[b] = min(max(i0 - 1 + b, 0), HN - 1);
        g_yidx[tid] = make_int4(idx[0], idx[1], idx[2], idx[3]);
        g_ywt [tid] = make_float4(w[0], w[1], w[2], w[3]);
    }

    // --- x taps: bin by x0, counting sort ---
    float x  = (g1[tid] + 1.0f) * 0.5f * (float)(WN - 1);
    float x0 = floorf(x);
    float t  = x - x0;
    int bin  = min(max((int)x0, 0), NB - 1);
    float w[4];
    cubic_w(t, w);

    if (tid < NB) sh_hist[tid] = 0;
    __syncthreads();
    int rank = atomicAdd(&sh_hist[bin], 1);
    __syncthreads();

    // Parallel inclusive scan over 256 bins
    if (tid < NB) sh_scan[tid] = sh_hist[tid];
    __syncthreads();
#pragma unroll
    for (int off = 1; off < NB; off <<= 1) {
        int v = 0;
        if (tid < NB && tid >= off) v = sh_scan[tid - off];
        __syncthreads();
        if (tid < NB) sh_scan[tid] += v;
        __syncthreads();
    }
    if (tid < NB) {
        int base = sh_scan[tid] - sh_hist[tid];
        sh_base[tid] = base;
        g_binstart[tid] = base;
        if (tid == NB - 1) g_binstart[NB] = sh_scan[tid];
    }
    __syncthreads();

    int pos = sh_base[bin] + rank;
    // w3 is reconstructed in the kernel as 1 - w0 - w1 - w2 (partition of unity)
    g_meta[pos] = make_float4(w[0], w[1], w[2], __int_as_float(tid));

    // balanced warp partition: wstart[q] = bin containing sorted entry q*32
    if (tid <= NWARP) {
        const int target = tid * (L1N / NWARP);
        int lo = 0, hi = NB;
        while (lo < hi) {
            int mid = (lo + hi) >> 1;
            int endv = (mid == NB - 1) ? L1N : sh_base[mid + 1];
            if (endv > target) hi = mid; else lo = mid + 1;
        }
        g_wstart[tid] = lo;
    }
}

// Fused kernel: one block = (c, 128-wide j tile), 1024 threads.
// Phase A: warp w owns f-group f=w (j = 4w..4w+3). Per j and per 128-x chunk:
//          4 coalesced LDG.128 along x -> 4 x-results -> 4 scalar swizzled STS
//          (4-way conflict, measured benign). 32 LDG.128/warp total (was 128 LDG.32).
// Phase B: balanced bin ranges (wstart), float4 register rotation
//          (1 conflict-free LDS.128 per bin), ONE LDS.128 metadata per entry,
//          w3 reconstructed, STG.128 streaming store.
__global__ void __launch_bounds__(1024, 1)
fused_kernel(const float* __restrict__ v, float* __restrict__ out) {
    extern __shared__ float smem[];
    float*  sY    = smem + OFF_SY;
    float4* sMETA = (float4*)(smem + OFF_META);
    int*    sBS   = (int*)(smem + OFF_BS);
    int*    sWS   = (int*)(smem + OFF_WS);

    const int tid  = threadIdx.x;
    const int lane = tid & 31;
    const int wid  = tid >> 5;             // 0..31
    const int jt = blockIdx.x * JT;
    const int c  = blockIdx.y;

    const float* vc = v + (size_t)c * (HN * WN);

    // table copy (overlaps phase-A loads; covered by the phase barrier)
    sMETA[tid] = g_meta[tid];
    if (tid < NB + 1) sBS[tid] = g_binstart[tid];
    if (tid < NWARP + 1) sWS[tid] = g_wstart[tid];

    // ---- Phase A ----
    {
        const int f = wid;                 // f-group
#pragma unroll
        for (int jj = 0; jj < 4; jj++) {
            const int jl = (f << 2) + jj;
            const int4   yi = g_yidx[jt + jl];
            const float4 wy = g_ywt [jt + jl];
            const float4* r0 = (const float4*)(vc + yi.x * WN);
            const float4* r1 = (const float4*)(vc + yi.y * WN);
            const float4* r2 = (const float4*)(vc + yi.z * WN);
            const float4* r3 = (const float4*)(vc + yi.w * WN);
#pragma unroll
            for (int ch = 0; ch < 2; ch++) {
                const int q = ch * 32 + lane;      // float4 index along x: 0..63
                const float4 v0 = __ldg(r0 + q);
                const float4 v1 = __ldg(r1 + q);
                const float4 v2 = __ldg(r2 + q);
                const float4 v3 = __ldg(r3 + q);
                float4 res;
                res.x = wy.x * v0.x + wy.y * v1.x + wy.z * v2.x + wy.w * v3.x;
                res.y = wy.x * v0.y + wy.y * v1.y + wy.z * v2.y + wy.w * v3.y;
                res.z = wy.x * v0.z + wy.y * v1.z + wy.z * v2.z + wy.w * v3.z;
                res.w = wy.x * v0.w + wy.y * v1.w + wy.z * v2.w + wy.w * v3.w;
                const int x0 = q << 2;             // rows x0..x0+3
                sY[(x0 + 0) * SROW + ((f ^ ((x0 + 0) & 31)) << 2) + jj] = res.x;
                sY[(x0 + 1) * SROW + ((f ^ ((x0 + 1) & 31)) << 2) + jj] = res.y;
                sY[(x0 + 2) * SROW + ((f ^ ((x0 + 2) & 31)) << 2) + jj] = res.z;
                sY[(x0 + 3) * SROW + ((f ^ ((x0 + 3) & 31)) << 2) + jj] = res.w;
            }
        }
    }
    __syncthreads();

    // ---- Phase B ----
    float* outc = out + ((size_t)c * L1N) * L0N + jt + (lane << 2);
    #define LOADROW(xx) (*(const float4*)(sY + (xx) * SROW + ((lane ^ ((xx) & 31)) << 2)))

    const int bs = sWS[wid];
    const int be = sWS[wid + 1];
    if (bs < be) {
        float4 a0 = LOADROW(max(bs - 1, 0));
        float4 a1 = LOADROW(bs);
        float4 a2 = LOADROW(min(bs + 1, WN - 1));

        int s = sBS[bs];
        for (int b = bs; b < be; b++) {
            const float4 a3 = LOADROW(min(b + 2, WN - 1));
            const int e = sBS[b + 1];

            int k = s;
            for (; k + 1 < e; k += 2) {
                const float4 mA = sMETA[k];
                const float4 mB = sMETA[k + 1];
                const int iA = __float_as_int(mA.w);
                const int iB = __float_as_int(mB.w);
                const float w3A = 1.0f - mA.x - mA.y - mA.z;
                const float w3B = 1.0f - mB.x - mB.y - mB.z;
                float4 accA, accB;
                accA.x = mA.x * a0.x + mA.y * a1.x + mA.z * a2.x + w3A * a3.x;
                accA.y = mA.x * a0.y + mA.y * a1.y + mA.z * a2.y + w3A * a3.y;
                accA.z = mA.x * a0.z + mA.y * a1.z + mA.z * a2.z + w3A * a3.z;
                accA.w = mA.x * a0.w + mA.y * a1.w + mA.z * a2.w + w3A * a3.w;
                accB.x = mB.x * a0.x + mB.y * a1.x + mB.z * a2.x + w3B * a3.x;
                accB.y = mB.x * a0.y + mB.y * a1.y + mB.z * a2.y + w3B * a3.y;
                accB.z = mB.x * a0.z + mB.y * a1.z + mB.z * a2.z + w3B * a3.z;
                accB.w = mB.x * a0.w + mB.y * a1.w + mB.z * a2.w + w3B * a3.w;
                __stcs((float4*)(outc + (size_t)iA * L0N), accA);
                __stcs((float4*)(outc + (size_t)iB * L0N), accB);
            }
            if (k < e) {
                const float4 m = sMETA[k];
                const int i = __float_as_int(m.w);
                const float w3 = 1.0f - m.x - m.y - m.z;
                float4 acc;
                acc.x = m.x * a0.x + m.y * a1.x + m.z * a2.x + w3 * a3.x;
                acc.y = m.x * a0.y + m.y * a1.y + m.z * a2.y + w3 * a3.y;
                acc.z = m.x * a0.z + m.y * a1.z + m.z * a2.z + w3 * a3.z;
                acc.w = m.x * a0.w + m.y * a1.w + m.z * a2.w + w3 * a3.w;
                __stcs((float4*)(outc + (size_t)i * L0N), acc);
            }
            s = e;
            a0 = a1; a1 = a2; a2 = a3;
        }
    }
    #undef LOADROW
}

extern "C" void kernel_launch(void* const* d_in, const int* in_sizes, int n_in,
                              void* d_out, int out_size) {
    const float* values = (const float*)d_in[0];   // (1,64,256,256)
    const float* g0     = (const float*)d_in[1];   // (1024,)
    const float* g1     = (const float*)d_in[2];   // (1024,)
    float* out = (float*)d_out;                    // (1,64,1024,1024)

    static int smem_set = 0;
    const int smem_bytes = SMEM_FLOATS * sizeof(float);  // ~148.6 KB
    if (!smem_set) {
        cudaFuncSetAttribute(fused_kernel,
                             cudaFuncAttributeMaxDynamicSharedMemorySize,
                             smem_bytes);
        smem_set = 1;
    }

    prep_kernel<<<1, 1024>>>(g0, g1);

    dim3 grid(L0N / JT, CN);               // (8, 64) = 512 blocks
    fused_kernel<<<grid, 1024, smem_bytes>>>(values, out);
}

// round 15
// speedup vs baseline: 1.1373x; 1.1373x over previous
#include <cuda_runtime.h>

// Problem constants (fixed by reference)
#define CN 64
#define HN 256
#define WN 256
#define L0N 1024   // g0 length (y samples), output innermost dim (j)
#define L1N 1024   // g1 length (x samples), output middle dim (i)
#define AC (-0.75f)

#define JT 64      // j-tile width per block
#define RS 66      // smem row stride in floats: 66 mod 32 = 2 -> 2-way STS conflict
#define NB 256     // x0 bins
#define NWRP 16    // warps per block

// Precomputed y tap indices / weights
__device__ int4   g_yidx[L0N];
__device__ float4 g_ywt [L0N];
// x samples sorted by x0 bin (counting sort)
__device__ int    g_binstart[NB + 1];
__device__ float4 g_swx[L1N];   // weights in sorted order
__device__ int    g_si [L1N];   // original i in sorted order
__device__ int    g_wstart[NWRP + 1];  // balanced contiguous bin ranges per warp

__device__ __forceinline__ void cubic_w(float t, float* w) {
    // Matches reference _cubic_weights exactly (A = -0.75)
    float t2 = t * t;
    float t3 = t2 * t;
    w[0] = AC * (t3 - 2.0f * t2 + t);
    w[1] = (AC + 2.0f) * t3 - (AC + 3.0f) * t2 + 1.0f;
    float s  = 1.0f - t;
    float s2 = s * s;
    w[2] = (AC + 2.0f) * s2 * s - (AC + 3.0f) * s2 + 1.0f;
    float u = 1.0f + s;
    w[3] = AC * (u * u * u) - 5.0f * AC * (u * u) + 8.0f * AC * u - 4.0f * AC;
}

// Single-block prep: y tables + counting sort of x samples by x0 (parallel scan)
// + balanced warp partition of the bins (by entry count).
__global__ void prep_kernel(const float* __restrict__ g0,
                            const float* __restrict__ g1) {
    __shared__ int sh_hist[NB];
    __shared__ int sh_scan[NB];
    __shared__ int sh_base[NB];
    const int tid = threadIdx.x;   // 0..1023

    // --- y taps ---
    {
        float x  = (g0[tid] + 1.0f) * 0.5f * (float)(HN - 1);
        float x0 = floorf(x);
        float t  = x - x0;
        int  i0  = (int)x0;
        float w[4];
        cubic_w(t, w);
        int idx[4];
#pragma unroll
        for (int b = 0; b < 4; b++) idx[b] = min(max(i0 - 1 + b, 0), HN - 1);
        g_yidx[tid] = make_int4(idx[0], idx[1], idx[2], idx[3]);
        g_ywt [tid] = make_float4(w[0], w[1], w[2], w[3]);
    }

    // --- x taps: bin by x0, counting sort ---
    float x  = (g1[tid] + 1.0f) * 0.5f * (float)(WN - 1);
    float x0 = floorf(x);
    float t  = x - x0;
    int bin  = min(max((int)x0, 0), NB - 1);
    float w[4];
    cubic_w(t, w);

    if (tid < NB) sh_hist[tid] = 0;
    __syncthreads();
    int rank = atomicAdd(&sh_hist[bin], 1);
    __syncthreads();

    // Parallel inclusive scan (Hillis-Steele) over 256 bins
    if (tid < NB) sh_scan[tid] = sh_hist[tid];
    __syncthreads();
#pragma unroll
    for (int off = 1; off < NB; off <<= 1) {
        int v = 0;
        if (tid < NB && tid >= off) v = sh_scan[tid - off];
        __syncthreads();
        if (tid < NB) sh_scan[tid] += v;
        __syncthreads();
    }
    if (tid < NB) {
        int base = sh_scan[tid] - sh_hist[tid];   // exclusive
        sh_base[tid] = base;
        g_binstart[tid] = base;
        if (tid == NB - 1) g_binstart[NB] = sh_scan[tid];
    }
    __syncthreads();

    int pos = sh_base[bin] + rank;
    g_swx[pos] = make_float4(w[0], w[1], w[2], w[3]);
    g_si [pos] = tid;

    // --- balanced warp partition: wstart[q] = first bin of warp q's range,
    //     chosen so each range holds ~64 sorted entries ---
    if (tid <= NWRP) {
        const int target = tid * (L1N / NWRP);    // 0, 64, ..., 1024
        int lo = 0, hi = NB;
        while (lo < hi) {
            int mid = (lo + hi) >> 1;
            int endv = (mid == NB - 1) ? L1N : sh_base[mid + 1];
            if (endv > target) hi = mid; else lo = mid + 1;
        }
        g_wstart[tid] = lo;                       // tid==NWRP -> 256
    }
}

// Fused kernel: one block = (c, 64-wide j tile). 512 threads, 3 blocks/SM.
// Phase A: sY[x][jl] = sum_b wy[j][b] * v[c][yi[j][b]][x]   (identical to R4)
// Phase B: warp sweeps its BALANCED contiguous bin range [wstart[w], wstart[w+1])
//          — ~64 entries each, straggler eliminated. Per bin: 4 LDS.64 taps;
//          per entry: 8 FFMA + STG.64 (float2, unroll-2 k-loop). Identical
//          inner loop to the 76.06us best.
__global__ void __launch_bounds__(512, 3)
fused_kernel(const float* __restrict__ v, float* __restrict__ out) {
    extern __shared__ float sY[];          // [256][RS]

    const int tid  = threadIdx.x;
    const int lane = tid & 31;
    const int wid  = tid >> 5;             // 0..15
    const int jt = blockIdx.x * JT;        // j tile base
    const int c  = blockIdx.y;

    const float* vc = v + (size_t)c * (HN * WN);

    // ---- Phase A: y-interpolation into smem ----
#pragma unroll
    for (int r = 0; r < 4; r++) {
        const int jl = wid + r * 16;       // 0..63
        const int4   yi = g_yidx[jt + jl];
        const float4 wy = g_ywt [jt + jl];
        const float* r0 = vc + yi.x * WN;
        const float* r1 = vc + yi.y * WN;
        const float* r2 = vc + yi.z * WN;
        const float* r3 = vc + yi.w * WN;
#pragma unroll
        for (int xc = 0; xc < 8; xc++) {
            const int x = xc * 32 + lane;
            float acc = wy.x * __ldg(r0 + x)
                      + wy.y * __ldg(r1 + x)
                      + wy.z * __ldg(r2 + x)
                      + wy.w * __ldg(r3 + x);
            sY[x * RS + jl] = acc;
        }
    }
    __syncthreads();

    // ---- Phase B: balanced contiguous bin range per warp, float2 along j ----
    const int jq = lane * 2;               // j offset in tile: 0..62
    float* outc = out + ((size_t)c * L1N) * L0N + jt + jq;

    const int bs = g_wstart[wid];
    const int be = g_wstart[wid + 1];

    for (int b = bs; b < be; b++) {
        const int s = g_binstart[b];
        const int e = g_binstart[b + 1];
        if (s == e) continue;

        const int rr0 = max(b - 1, 0);
        const int rr2 = min(b + 1, WN - 1);
        const int rr3 = min(b + 2, WN - 1);

        const float2 a0 = *(const float2*)(sY + rr0 * RS + jq);
        const float2 a1 = *(const float2*)(sY + b   * RS + jq);
        const float2 a2 = *(const float2*)(sY + rr2 * RS + jq);
        const float2 a3 = *(const float2*)(sY + rr3 * RS + jq);

        int k = s;
        for (; k + 1 < e; k += 2) {
            const int    iA  = g_si [k];
            const float4 wxA = g_swx[k];
            const int    iB  = g_si [k + 1];
            const float4 wxB = g_swx[k + 1];
            float2 accA, accB;
            accA.x = wxA.x * a0.x + wxA.y * a1.x + wxA.z * a2.x + wxA.w * a3.x;
            accA.y = wxA.x * a0.y + wxA.y * a1.y + wxA.z * a2.y + wxA.w * a3.y;
            accB.x = wxB.x * a0.x + wxB.y * a1.x + wxB.z * a2.x + wxB.w * a3.x;
            accB.y = wxB.x * a0.y + wxB.y * a1.y + wxB.z * a2.y + wxB.w * a3.y;
            *(float2*)(outc + (size_t)iA * L0N) = accA;
            *(float2*)(outc + (size_t)iB * L0N) = accB;
        }
        if (k < e) {
            const int    i  = g_si [k];
            const float4 wx = g_swx[k];
            float2 acc;
            acc.x = wx.x * a0.x + wx.y * a1.x + wx.z * a2.x + wx.w * a3.x;
            acc.y = wx.x * a0.y + wx.y * a1.y + wx.z * a2.y + wx.w * a3.y;
            *(float2*)(outc + (size_t)i * L0N) = acc;
        }
    }
}

extern "C" void kernel_launch(void* const* d_in, const int* in_sizes, int n_in,
                              void* d_out, int out_size) {
    const float* values = (const float*)d_in[0];   // (1,64,256,256)
    const float* g0     = (const float*)d_in[1];   // (1024,)
    const float* g1     = (const float*)d_in[2];   // (1024,)
    float* out = (float*)d_out;                    // (1,64,1024,1024)

    static int smem_set = 0;
    const int smem_bytes = HN * RS * sizeof(float);  // 256*66*4 = 67584
    if (!smem_set) {
        cudaFuncSetAttribute(fused_kernel,
                             cudaFuncAttributeMaxDynamicSharedMemorySize,
                             smem_bytes);
        smem_set = 1;
    }

    prep_kernel<<<1, 1024>>>(g0, g1);

    dim3 grid(L0N / JT, CN);               // (16, 64) = 1024 blocks
    fused_kernel<<<grid, 512, smem_bytes>>>(values, out);
}

// round 16
// speedup vs baseline: 1.1681x; 1.0271x over previous
#include <cuda_runtime.h>

// Problem constants (fixed by reference)
#define CN 64
#define HN 256
#define WN 256
#define L0N 1024   // g0 length (y samples), output innermost dim (j)
#define L1N 1024   // g1 length (x samples), output middle dim (i)
#define AC (-0.75f)

#define JT 128     // j-tile width per block (one float4 per lane covers it)
#define NB 256     // x0 bins
#define SROW 128   // floats per smem row; XOR swizzle f' = f ^ (x&31) on float4 units

// Precomputed tap indices / weights
__device__ int4   g_yidx[L0N];
__device__ float4 g_ywt [L0N];
// x samples sorted by x0 bin (counting sort)
__device__ int    g_binstart[NB + 1];
__device__ float4 g_swx[L1N];   // weights in sorted order
__device__ int    g_si [L1N];   // original i in sorted order

__device__ __forceinline__ void cubic_w(float t, float* w) {
    // Matches reference _cubic_weights exactly (A = -0.75)
    float t2 = t * t;
    float t3 = t2 * t;
    w[0] = AC * (t3 - 2.0f * t2 + t);
    w[1] = (AC + 2.0f) * t3 - (AC + 3.0f) * t2 + 1.0f;
    float s  = 1.0f - t;
    float s2 = s * s;
    w[2] = (AC + 2.0f) * s2 * s - (AC + 3.0f) * s2 + 1.0f;
    float u = 1.0f + s;
    w[3] = AC * (u * u * u) - 5.0f * AC * (u * u) + 8.0f * AC * u - 4.0f * AC;
}

// Single-block prep: y tables + counting sort of x samples by x0 (parallel scan).
// Launched with the SAME dynamic-smem size as fused_kernel so the CUDA graph
// replays without an SM shared-memory carveout reconfiguration between them.
__global__ void prep_kernel(const float* __restrict__ g0,
                            const float* __restrict__ g1) {
    extern __shared__ float dummy[];   // unused; forces matching carveout
    __shared__ int sh_hist[NB];
    __shared__ int sh_scan[NB];
    __shared__ int sh_base[NB];
    const int tid = threadIdx.x;   // 0..1023

    // --- y taps ---
    {
        float x  = (g0[tid] + 1.0f) * 0.5f * (float)(HN - 1);
        float x0 = floorf(x);
        float t  = x - x0;
        int  i0  = (int)x0;
        float w[4];
        cubic_w(t, w);
        int idx[4];
#pragma unroll
        for (int b = 0; b < 4; b++) idx[b] = min(max(i0 - 1 + b, 0), HN - 1);
        g_yidx[tid] = make_int4(idx[0], idx[1], idx[2], idx[3]);
        g_ywt [tid] = make_float4(w[0], w[1], w[2], w[3]);
    }

    // --- x taps: bin by x0, counting sort ---
    float x  = (g1[tid] + 1.0f) * 0.5f * (float)(WN - 1);
    float x0 = floorf(x);
    float t  = x - x0;
    int bin  = min(max((int)x0, 0), NB - 1);
    float w[4];
    cubic_w(t, w);

    if (tid < NB) sh_hist[tid] = 0;
    __syncthreads();
    int rank = atomicAdd(&sh_hist[bin], 1);
    __syncthreads();

    // Parallel inclusive scan (Hillis-Steele) over 256 bins
    if (tid < NB) sh_scan[tid] = sh_hist[tid];
    __syncthreads();
#pragma unroll
    for (int off = 1; off < NB; off <<= 1) {
        int v = 0;
        if (tid < NB && tid >= off) v = sh_scan[tid - off];
        __syncthreads();
        if (tid < NB) sh_scan[tid] += v;
        __syncthreads();
    }
    if (tid < NB) {
        int base = sh_scan[tid] - sh_hist[tid];   // exclusive
        sh_base[tid] = base;
        g_binstart[tid] = base;
        if (tid == NB - 1) g_binstart[NB] = sh_scan[tid];
    }
    __syncthreads();

    int pos = sh_base[bin] + rank;
    g_swx[pos] = make_float4(w[0], w[1], w[2], w[3]);
    g_si [pos] = tid;
}

// Fused kernel: one block = (c, 128-wide j tile), 1024 threads, 128 KB smem.
// Phase A: sY[x][j] = sum_b wy[j][b] * v[c][yi[j][b]][x]   (swizzled store)
// Phase B: warp sweeps 8 consecutive x0-bins, 4 tap rows held as float4 regs
//          (rotation: 1 LDS.128 per bin). One STG.128 per output row per warp.
__global__ void __launch_bounds__(1024, 1)
fused_kernel(const float* __restrict__ v, float* __restrict__ out) {
    extern __shared__ float sY[];          // [256][128] swizzled

    const int tid  = threadIdx.x;
    const int lane = tid & 31;
    const int wid  = tid >> 5;             // 0..31
    const int jt = blockIdx.x * JT;        // j tile base
    const int c  = blockIdx.y;

    const float* vc = v + (size_t)c * (HN * WN);

    // ---- Phase A: y-interpolation into swizzled smem ----
#pragma unroll
    for (int jj = 0; jj < 4; jj++) {
        const int jl = (wid << 2) + jj;    // 0..127
        const int4   yi = g_yidx[jt + jl];
        const float4 wy = g_ywt [jt + jl];
        const float* r0 = vc + yi.x * WN;
        const float* r1 = vc + yi.y * WN;
        const float* r2 = vc + yi.z * WN;
        const float* r3 = vc + yi.w * WN;
        const int f    = jl >> 2;          // float4 index 0..31
        const int jsub = jl & 3;
#pragma unroll
        for (int xc = 0; xc < 8; xc++) {
            const int x = xc * 32 + lane;
            float acc = wy.x * __ldg(r0 + x)
                      + wy.y * __ldg(r1 + x)
                      + wy.z * __ldg(r2 + x)
                      + wy.w * __ldg(r3 + x);
            sY[x * SROW + ((f ^ (x & 31)) << 2) + jsub] = acc;
        }
    }
    __syncthreads();

    // ---- Phase B: 8 consecutive bins per warp, float4 register rotation ----
    float* outc = out + ((size_t)c * L1N) * L0N + jt + (lane << 2);

    const int b0 = wid * 8;                // this warp's first bin

    #define LOADROW(x) (*(const float4*)(sY + (x) * SROW + ((lane ^ ((x) & 31)) << 2)))

    float4 a0 = LOADROW(max(b0 - 1, 0));
    float4 a1 = LOADROW(b0);
    float4 a2 = LOADROW(b0 + 1);           // b0 <= 248, no clamp needed

    int s = g_binstart[b0];

#pragma unroll
    for (int bb = 0; bb < 8; bb++) {
        const int b = b0 + bb;
        const float4 a3 = LOADROW(min(b + 2, WN - 1));
        const int e = g_binstart[b + 1];

        int k = s;
        for (; k + 1 < e; k += 2) {
            const int    iA  = g_si [k];
            const float4 wxA = g_swx[k];
            const int    iB  = g_si [k + 1];
            const float4 wxB = g_swx[k + 1];
            float4 accA, accB;
            accA.x = wxA.x * a0.x + wxA.y * a1.x + wxA.z * a2.x + wxA.w * a3.x;
            accA.y = wxA.x * a0.y + wxA.y * a1.y + wxA.z * a2.y + wxA.w * a3.y;
            accA.z = wxA.x * a0.z + wxA.y * a1.z + wxA.z * a2.z + wxA.w * a3.z;
            accA.w = wxA.x * a0.w + wxA.y * a1.w + wxA.z * a2.w + wxA.w * a3.w;
            accB.x = wxB.x * a0.x + wxB.y * a1.x + wxB.z * a2.x + wxB.w * a3.x;
            accB.y = wxB.x * a0.y + wxB.y * a1.y + wxB.z * a2.y + wxB.w * a3.y;
            accB.z = wxB.x * a0.z + wxB.y * a1.z + wxB.z * a2.z + wxB.w * a3.z;
            accB.w = wxB.x * a0.w + wxB.y * a1.w + wxB.z * a2.w + wxB.w * a3.w;
            *(float4*)(outc + (size_t)iA * L0N) = accA;
            *(float4*)(outc + (size_t)iB * L0N) = accB;
        }
        if (k < e) {
            const int    i  = g_si [k];
            const float4 wx = g_swx[k];
            float4 acc;
            acc.x = wx.x * a0.x + wx.y * a1.x + wx.z * a2.x + wx.w * a3.x;
            acc.y = wx.x * a0.y + wx.y * a1.y + wx.z * a2.y + wx.w * a3.y;
            acc.z = wx.x * a0.z + wx.y * a1.z + wx.z * a2.z + wx.w * a3.z;
            acc.w = wx.x * a0.w + wx.y * a1.w + wx.z * a2.w + wx.w * a3.w;
            *(float4*)(outc + (size_t)i * L0N) = acc;
        }
        s = e;
        a0 = a1; a1 = a2; a2 = a3;
    }
    #undef LOADROW
}

extern "C" void kernel_launch(void* const* d_in, const int* in_sizes, int n_in,
                              void* d_out, int out_size) {
    const float* values = (const float*)d_in[0];   // (1,64,256,256)
    const float* g0     = (const float*)d_in[1];   // (1024,)
    const float* g1     = (const float*)d_in[2];   // (1024,)
    float* out = (float*)d_out;                    // (1,64,1024,1024)

    static int smem_set = 0;
    const int smem_bytes = HN * SROW * sizeof(float);  // 256*128*4 = 131072
    if (!smem_set) {
        cudaFuncSetAttribute(fused_kernel,
                             cudaFuncAttributeMaxDynamicSharedMemorySize,
                             smem_bytes);
        cudaFuncSetAttribute(prep_kernel,
                             cudaFuncAttributeMaxDynamicSharedMemorySize,
                             smem_bytes);
        smem_set = 1;
    }

    // prep gets the SAME dynamic smem size -> no carveout reconfig in the graph
    prep_kernel<<<1, 1024, smem_bytes>>>(g0, g1);

    dim3 grid(L0N / JT, CN);               // (8, 64) = 512 blocks
    fused_kernel<<<grid, 1024, smem_bytes>>>(values, out);
}